// round 16
// baseline (speedup 1.0000x reference)
#include <cuda_runtime.h>
#include <cuda_fp16.h>
#include <math.h>
#include <stdint.h>

#define B_  4
#define T_  2048
#define V_  2048
#define D_  512
#define H_  8
#define L_  4
#define HD_ 64
#define NT_ (B_ * T_ * D_)   // 4M elems
#define DD_ (D_ * D_)

// ---- global scratch (no allocation allowed) ----
__device__ __align__(16) __half g_hh[NT_], g_hl[NT_];
__device__ __align__(16) __half g_qh[NT_], g_ql[NT_];
__device__ __align__(16) __half g_k1[NT_];
__device__ __align__(16) __half g_v1[NT_];
__device__ __align__(16) __half g_oh[NT_], g_ol[NT_];
__device__ __align__(16) __half g_te1[D_ * V_];
__device__ __align__(16) __half g_wq1[DD_];            // layer-0 weights only
__device__ __align__(16) __half g_wk1[DD_];
__device__ __align__(16) __half g_wv1[DD_];
__device__ __align__(16) __half g_wpT[3 * DD_];        // Wp^T fp16, layers 0..2
__device__ __align__(16) __half g_uq[3 * DD_];         // folded W_{l+1}·Wp_l
__device__ __align__(16) __half g_uk[3 * DD_];
__device__ __align__(16) __half g_uv[3 * DD_];
__device__ __align__(16) float  g_hlast[B_ * D_];

// ---------------------------------------------------------------------------
__device__ __forceinline__ void split2h(float x, float y, uint32_t& h, uint32_t& l)
{
    __half2 hv = __float22half2_rn(make_float2(x, y));
    float2 hf = __half22float2(hv);
    __half2 lv = __float22half2_rn(make_float2(x - hf.x, y - hf.y));
    h = *reinterpret_cast<uint32_t*>(&hv);
    l = *reinterpret_cast<uint32_t*>(&lv);
}

__device__ __forceinline__ uint32_t cvt2h(float x, float y)
{
    __half2 v = __float22half2_rn(make_float2(x, y));
    return *reinterpret_cast<uint32_t*>(&v);
}

__device__ __forceinline__ float ex2(float x)
{
    float y;
    asm("ex2.approx.f32 %0, %1;" : "=f"(y) : "f"(x));
    return y;
}

__device__ __forceinline__ void mma16816(float* d, const uint32_t* a, const uint32_t* b)
{
    asm volatile(
        "mma.sync.aligned.m16n8k16.row.col.f32.f16.f16.f32 "
        "{%0,%1,%2,%3}, {%4,%5,%6,%7}, {%8,%9}, {%0,%1,%2,%3};\n"
        : "+f"(d[0]), "+f"(d[1]), "+f"(d[2]), "+f"(d[3])
        : "r"(a[0]), "r"(a[1]), "r"(a[2]), "r"(a[3]), "r"(b[0]), "r"(b[1]));
}

__device__ __forceinline__ void ldsm4(uint32_t* r, uint32_t addr)
{
    asm volatile("ldmatrix.sync.aligned.m8n8.x4.shared.b16 {%0,%1,%2,%3}, [%4];"
                 : "=r"(r[0]), "=r"(r[1]), "=r"(r[2]), "=r"(r[3]) : "r"(addr));
}
__device__ __forceinline__ void ldsm4t(uint32_t* r, uint32_t addr)
{
    asm volatile("ldmatrix.sync.aligned.m8n8.x4.trans.shared.b16 {%0,%1,%2,%3}, [%4];"
                 : "=r"(r[0]), "=r"(r[1]), "=r"(r[2]), "=r"(r[3]) : "r"(addr));
}

__device__ __forceinline__ uint32_t smem_u32(const void* p)
{
    uint32_t a;
    asm("{ .reg .u64 t; cvta.to.shared.u64 t, %1; cvt.u32.u64 %0, t; }" : "=r"(a) : "l"(p));
    return a;
}

__device__ __forceinline__ void cp16(uint32_t saddr, const void* gaddr)
{
    asm volatile("cp.async.cg.shared.global [%0], [%1], 16;" :: "r"(saddr), "l"(gaddr));
}

// ---------------------------------------------------------------------------
__global__ void __launch_bounds__(256) tohalf_kernel(
    const float4* __restrict__ src, uint2* __restrict__ dst, int n4)
{
    int i = blockIdx.x * 256 + threadIdx.x;
    if (i < n4) {
        float4 f = src[i];
        dst[i] = make_uint2(cvt2h(f.x, f.y), cvt2h(f.z, f.w));
    }
}

// ---------------------------------------------------------------------------
// Transpose Wp (fp32 [D,D]) -> wpT (fp16 [D,D]), layers 0..2.
// ---------------------------------------------------------------------------
__global__ void __launch_bounds__(256) transpose_kernel(
    const float* __restrict__ Wp, __half* __restrict__ wpT)
{
    __shared__ float tile[32][33];
    const int l  = blockIdx.z;
    const int x0 = blockIdx.x * 32;
    const int y0 = blockIdx.y * 32;
    const float* S = Wp + (size_t)l * DD_;
    __half* Dp = wpT + (size_t)l * DD_;
    const int tx = threadIdx.x & 31;
    const int ty = threadIdx.x >> 5;
#pragma unroll
    for (int i = ty; i < 32; i += 8)
        tile[i][tx] = S[(size_t)(y0 + i) * D_ + x0 + tx];
    __syncthreads();
#pragma unroll
    for (int i = ty; i < 32; i += 8)
        Dp[(size_t)(x0 + i) * D_ + y0 + tx] = __float2half(tile[tx][i]);
}

#define GST 24          // smem row stride in fp16 (48 bytes)
#define GBUF 3072       // 128 * 24 fp16 per (part, stage)

// ---------------------------------------------------------------------------
// Weight-combine GEMM: U_x,l = W_x,{l+1} @ Wp_l
// ---------------------------------------------------------------------------
__global__ void __launch_bounds__(256) gemm_combine(
    const float* __restrict__ Wq, const float* __restrict__ Wk,
    const float* __restrict__ Wv, const __half* __restrict__ wpT,
    __half* __restrict__ Uq, __half* __restrict__ Uk, __half* __restrict__ Uv)
{
    __shared__ __align__(16) __half sm[2][3][GBUF];

    const int z = blockIdx.z;
    const int l = z / 3, xx = z % 3;
    const float* Af = ((xx == 0) ? Wq : (xx == 1) ? Wk : Wv) + (size_t)(l + 1) * DD_;
    const __half* Bm = wpT + (size_t)l * DD_;
    __half* C = ((xx == 0) ? Uq : (xx == 1) ? Uk : Uv) + (size_t)l * DD_;
    const int N = D_, K = D_;

    const int tid  = threadIdx.x;
    const int lane = tid & 31;
    const int wid  = tid >> 5;
    const int wm   = (wid & 3) * 32;
    const int wn   = (wid >> 2) * 64;
    const int bm   = blockIdx.y * 128;
    const int bn   = blockIdx.x * 128;
    const int g    = lane >> 2;
    const int j    = lane & 3;

    const int lrow  = tid >> 1;
    const int lhalf = tid & 1;
    const float* pAf = Af + (size_t)(bm + lrow) * K + lhalf * 8;
    const __half* pB = Bm + (size_t)(bn + lrow) * K + lhalf * 8;
    const int sidx = lrow * GST + lhalf * 8;

    const int lr8  = (lane & 7) + ((lane >> 3) & 1) * 8;
    const int lc16 = (lane >> 4) * 16;
    const uint32_t smbase = smem_u32(&sm[0][0][0]);
    uint32_t offA[2], offB[4];
#pragma unroll
    for (int mt = 0; mt < 2; mt++) offA[mt] = (wm + mt * 16 + lr8) * 48 + lc16;
#pragma unroll
    for (int np = 0; np < 4; np++) offB[np] = (wn + np * 16 + lr8) * 48 + lc16;

    float acc[2][8][4];
#pragma unroll
    for (int mt = 0; mt < 2; mt++)
#pragma unroll
        for (int nt = 0; nt < 8; nt++)
#pragma unroll
            for (int i = 0; i < 4; i++) acc[mt][nt][i] = 0.f;

    const int KT = K >> 4;

    {
        float4 f0 = *(const float4*)(pAf);
        float4 f1 = *(const float4*)(pAf + 4);
        uint32_t h[4], l4[4];
        split2h(f0.x, f0.y, h[0], l4[0]);
        split2h(f0.z, f0.w, h[1], l4[1]);
        split2h(f1.x, f1.y, h[2], l4[2]);
        split2h(f1.z, f1.w, h[3], l4[3]);
        *(uint4*)&sm[0][0][sidx] = make_uint4(h[0], h[1], h[2], h[3]);
        *(uint4*)&sm[0][1][sidx] = make_uint4(l4[0], l4[1], l4[2], l4[3]);
        *(uint4*)&sm[0][2][sidx] = *(const uint4*)pB;
    }
    __syncthreads();

    for (int ks = 0; ks < KT; ks++) {
        const int cur = ks & 1, nxt = cur ^ 1;

        float4 rf0, rf1;
        uint4 rb;
        if (ks + 1 < KT) {
            int k0 = (ks + 1) << 4;
            rf0 = *(const float4*)(pAf + k0);
            rf1 = *(const float4*)(pAf + k0 + 4);
            rb  = *(const uint4*)(pB + k0);
        }

        const uint32_t sb = smbase + cur * (3 * GBUF * 2);
        uint32_t fah[2][4], fal[2][4];
#pragma unroll
        for (int mt = 0; mt < 2; mt++) {
            ldsm4(fah[mt], sb + 0 * (GBUF * 2) + offA[mt]);
            ldsm4(fal[mt], sb + 1 * (GBUF * 2) + offA[mt]);
        }
#pragma unroll
        for (int np = 0; np < 4; np++) {
            uint32_t bh[4];
            ldsm4(bh, sb + 2 * (GBUF * 2) + offB[np]);
            uint32_t bA[2] = { bh[0], bh[2] }, bB[2] = { bh[1], bh[3] };
#pragma unroll
            for (int mt = 0; mt < 2; mt++) {
                mma16816(acc[mt][np * 2],     fah[mt], bA);
                mma16816(acc[mt][np * 2],     fal[mt], bA);
                mma16816(acc[mt][np * 2 + 1], fah[mt], bB);
                mma16816(acc[mt][np * 2 + 1], fal[mt], bB);
            }
        }

        if (ks + 1 < KT) {
            uint32_t h[4], l4[4];
            split2h(rf0.x, rf0.y, h[0], l4[0]);
            split2h(rf0.z, rf0.w, h[1], l4[1]);
            split2h(rf1.x, rf1.y, h[2], l4[2]);
            split2h(rf1.z, rf1.w, h[3], l4[3]);
            *(uint4*)&sm[nxt][0][sidx] = make_uint4(h[0], h[1], h[2], h[3]);
            *(uint4*)&sm[nxt][1][sidx] = make_uint4(l4[0], l4[1], l4[2], l4[3]);
            *(uint4*)&sm[nxt][2][sidx] = rb;
        }
        __syncthreads();
    }

#pragma unroll
    for (int mt = 0; mt < 2; mt++) {
#pragma unroll
        for (int nt = 0; nt < 8; nt++) {
            int row = bm + wm + mt * 16 + g;
            int col = bn + wn + nt * 8 + j * 2;
            size_t i0 = (size_t)row * N + col;
            size_t i1 = (size_t)(row + 8) * N + col;
            *(uint32_t*)&C[i0] = cvt2h(acc[mt][nt][0], acc[mt][nt][1]);
            *(uint32_t*)&C[i1] = cvt2h(acc[mt][nt][2], acc[mt][nt][3]);
        }
    }
}

// ---------------------------------------------------------------------------
// Fused QKV GEMM: z=0 -> q (hi/lo, 2-term), z=1 -> k (single out, 1-term),
// z=2 -> v (single out, 2-term).
// ---------------------------------------------------------------------------
__global__ void __launch_bounds__(256, 2) gemm_qkv(
    const __half* __restrict__ Ah, const __half* __restrict__ Al,
    const __half* __restrict__ W0, const __half* __restrict__ W1,
    const __half* __restrict__ W2,
    __half* __restrict__ Qhi, __half* __restrict__ Qlo,
    __half* __restrict__ K1, __half* __restrict__ V1,
    float alpha)
{
    __shared__ __align__(16) __half sm[2][3][GBUF];

    const int z = blockIdx.z;
    const __half* Bm = (z == 0) ? W0 : (z == 1) ? W1 : W2;
    __half* Chi = (z == 0) ? Qhi : (z == 1) ? K1 : V1;
    __half* Clo = (z == 0) ? Qlo : nullptr;
    const bool useAl = (z != 1);   // K projection: drop the A-lo term
    const int N = D_, K = D_;

    const int tid  = threadIdx.x;
    const int lane = tid & 31;
    const int wid  = tid >> 5;
    const int wm   = (wid & 3) * 32;
    const int wn   = (wid >> 2) * 64;
    const int bm   = blockIdx.y * 128;
    const int bn   = blockIdx.x * 128;
    const int g    = lane >> 2;
    const int j    = lane & 3;

    const int lrow  = tid >> 1;
    const int lhalf = tid & 1;
    const __half* pAh = Ah + (size_t)(bm + lrow) * K + lhalf * 8;
    const __half* pAl = Al + (size_t)(bm + lrow) * K + lhalf * 8;
    const __half* pB  = Bm + (size_t)(bn + lrow) * K + lhalf * 8;
    const int sidx = lrow * GST + lhalf * 8;

    const int lr8  = (lane & 7) + ((lane >> 3) & 1) * 8;
    const int lc16 = (lane >> 4) * 16;
    const uint32_t smbase = smem_u32(&sm[0][0][0]);
    uint32_t offA[2], offB[4];
#pragma unroll
    for (int mt = 0; mt < 2; mt++) offA[mt] = (wm + mt * 16 + lr8) * 48 + lc16;
#pragma unroll
    for (int np = 0; np < 4; np++) offB[np] = (wn + np * 16 + lr8) * 48 + lc16;

    float acc[2][8][4];
#pragma unroll
    for (int mt = 0; mt < 2; mt++)
#pragma unroll
        for (int nt = 0; nt < 8; nt++)
#pragma unroll
            for (int i = 0; i < 4; i++) acc[mt][nt][i] = 0.f;

    const int KT = K >> 4;

    {
        *(uint4*)&sm[0][0][sidx] = *(const uint4*)pAh;
        *(uint4*)&sm[0][1][sidx] = *(const uint4*)pAl;
        *(uint4*)&sm[0][2][sidx] = *(const uint4*)pB;
    }
    __syncthreads();

    for (int ks = 0; ks < KT; ks++) {
        const int cur = ks & 1, nxt = cur ^ 1;

        uint4 rah, ral, rb;
        if (ks + 1 < KT) {
            int k0 = (ks + 1) << 4;
            rah = *(const uint4*)(pAh + k0);
            ral = *(const uint4*)(pAl + k0);
            rb  = *(const uint4*)(pB + k0);
        }

        const uint32_t sb = smbase + cur * (3 * GBUF * 2);
        uint32_t fah[2][4], fal[2][4];
#pragma unroll
        for (int mt = 0; mt < 2; mt++) {
            ldsm4(fah[mt], sb + 0 * (GBUF * 2) + offA[mt]);
            ldsm4(fal[mt], sb + 1 * (GBUF * 2) + offA[mt]);
        }
#pragma unroll
        for (int np = 0; np < 4; np++) {
            uint32_t bh[4];
            ldsm4(bh, sb + 2 * (GBUF * 2) + offB[np]);
            uint32_t bA[2] = { bh[0], bh[2] }, bB[2] = { bh[1], bh[3] };
#pragma unroll
            for (int mt = 0; mt < 2; mt++) {
                mma16816(acc[mt][np * 2],     fah[mt], bA);
                mma16816(acc[mt][np * 2 + 1], fah[mt], bB);
                if (useAl) {
                    mma16816(acc[mt][np * 2],     fal[mt], bA);
                    mma16816(acc[mt][np * 2 + 1], fal[mt], bB);
                }
            }
        }

        if (ks + 1 < KT) {
            *(uint4*)&sm[nxt][0][sidx] = rah;
            *(uint4*)&sm[nxt][1][sidx] = ral;
            *(uint4*)&sm[nxt][2][sidx] = rb;
        }
        __syncthreads();
    }

#pragma unroll
    for (int mt = 0; mt < 2; mt++) {
#pragma unroll
        for (int nt = 0; nt < 8; nt++) {
            int row = bm + wm + mt * 16 + g;
            int col = bn + wn + nt * 8 + j * 2;
            float2 v0 = make_float2(acc[mt][nt][0] * alpha, acc[mt][nt][1] * alpha);
            float2 v1 = make_float2(acc[mt][nt][2] * alpha, acc[mt][nt][3] * alpha);
            size_t i0 = (size_t)row * N + col;
            size_t i1 = (size_t)(row + 8) * N + col;
            if (Clo) {
                uint32_t h, l;
                split2h(v0.x, v0.y, h, l);
                *(uint32_t*)&Chi[i0] = h; *(uint32_t*)&Clo[i0] = l;
                split2h(v1.x, v1.y, h, l);
                *(uint32_t*)&Chi[i1] = h; *(uint32_t*)&Clo[i1] = l;
            } else {
                *(uint32_t*)&Chi[i0] = cvt2h(v0.x, v0.y);
                *(uint32_t*)&Chi[i1] = cvt2h(v1.x, v1.y);
            }
        }
    }
}

// ---------------------------------------------------------------------------
// Embed GEMM: A fp32 (x) split inline; B = te single fp16.
// ---------------------------------------------------------------------------
__global__ void __launch_bounds__(256, 2) gemm_nt_f32a(
    const float* __restrict__ Af, const __half* __restrict__ Bm,
    __half* __restrict__ Chi, __half* __restrict__ Clo,
    const float* __restrict__ bias, int M, int N, int K, float alpha)
{
    __shared__ __align__(16) __half sm[2][3][GBUF];

    const int tid  = threadIdx.x;
    const int lane = tid & 31;
    const int wid  = tid >> 5;
    const int wm   = (wid & 3) * 32;
    const int wn   = (wid >> 2) * 64;
    const int bm   = blockIdx.y * 128;
    const int bn   = blockIdx.x * 128;
    const int g    = lane >> 2;
    const int j    = lane & 3;

    const int lrow  = tid >> 1;
    const int lhalf = tid & 1;
    const float* pAf = Af + (size_t)(bm + lrow) * K + lhalf * 8;
    const __half* pB = Bm + (size_t)(bn + lrow) * K + lhalf * 8;
    const int sidx = lrow * GST + lhalf * 8;

    const int lr8  = (lane & 7) + ((lane >> 3) & 1) * 8;
    const int lc16 = (lane >> 4) * 16;
    const uint32_t smbase = smem_u32(&sm[0][0][0]);
    uint32_t offA[2], offB[4];
#pragma unroll
    for (int mt = 0; mt < 2; mt++) offA[mt] = (wm + mt * 16 + lr8) * 48 + lc16;
#pragma unroll
    for (int np = 0; np < 4; np++) offB[np] = (wn + np * 16 + lr8) * 48 + lc16;

    float acc[2][8][4];
#pragma unroll
    for (int mt = 0; mt < 2; mt++)
#pragma unroll
        for (int nt = 0; nt < 8; nt++)
#pragma unroll
            for (int i = 0; i < 4; i++) acc[mt][nt][i] = 0.f;

    const int KT = K >> 4;

    {
        float4 f0 = *(const float4*)(pAf);
        float4 f1 = *(const float4*)(pAf + 4);
        uint32_t h[4], l[4];
        split2h(f0.x, f0.y, h[0], l[0]);
        split2h(f0.z, f0.w, h[1], l[1]);
        split2h(f1.x, f1.y, h[2], l[2]);
        split2h(f1.z, f1.w, h[3], l[3]);
        *(uint4*)&sm[0][0][sidx] = make_uint4(h[0], h[1], h[2], h[3]);
        *(uint4*)&sm[0][1][sidx] = make_uint4(l[0], l[1], l[2], l[3]);
        *(uint4*)&sm[0][2][sidx] = *(const uint4*)pB;
    }
    __syncthreads();

    for (int ks = 0; ks < KT; ks++) {
        const int cur = ks & 1, nxt = cur ^ 1;

        float4 rf0, rf1;
        uint4 rb;
        if (ks + 1 < KT) {
            int k0 = (ks + 1) << 4;
            rf0 = *(const float4*)(pAf + k0);
            rf1 = *(const float4*)(pAf + k0 + 4);
            rb  = *(const uint4*)(pB + k0);
        }

        const uint32_t sb = smbase + cur * (3 * GBUF * 2);
        uint32_t fah[2][4], fal[2][4];
#pragma unroll
        for (int mt = 0; mt < 2; mt++) {
            ldsm4(fah[mt], sb + 0 * (GBUF * 2) + offA[mt]);
            ldsm4(fal[mt], sb + 1 * (GBUF * 2) + offA[mt]);
        }
#pragma unroll
        for (int np = 0; np < 4; np++) {
            uint32_t bh[4];
            ldsm4(bh, sb + 2 * (GBUF * 2) + offB[np]);
            uint32_t bA[2] = { bh[0], bh[2] }, bB[2] = { bh[1], bh[3] };
#pragma unroll
            for (int mt = 0; mt < 2; mt++) {
                mma16816(acc[mt][np * 2],     fah[mt], bA);
                mma16816(acc[mt][np * 2],     fal[mt], bA);
                mma16816(acc[mt][np * 2 + 1], fah[mt], bB);
                mma16816(acc[mt][np * 2 + 1], fal[mt], bB);
            }
        }

        if (ks + 1 < KT) {
            uint32_t h[4], l[4];
            split2h(rf0.x, rf0.y, h[0], l[0]);
            split2h(rf0.z, rf0.w, h[1], l[1]);
            split2h(rf1.x, rf1.y, h[2], l[2]);
            split2h(rf1.z, rf1.w, h[3], l[3]);
            *(uint4*)&sm[nxt][0][sidx] = make_uint4(h[0], h[1], h[2], h[3]);
            *(uint4*)&sm[nxt][1][sidx] = make_uint4(l[0], l[1], l[2], l[3]);
            *(uint4*)&sm[nxt][2][sidx] = rb;
        }
        __syncthreads();
    }

#pragma unroll
    for (int mt = 0; mt < 2; mt++) {
#pragma unroll
        for (int nt = 0; nt < 8; nt++) {
            int row = bm + wm + mt * 16 + g;
            int col = bn + wn + nt * 8 + j * 2;
            float2 v0 = make_float2(acc[mt][nt][0] * alpha, acc[mt][nt][1] * alpha);
            float2 v1 = make_float2(acc[mt][nt][2] * alpha, acc[mt][nt][3] * alpha);
            const float* b0 = bias + (size_t)(row & (T_ - 1)) * N + col;
            const float* b1 = bias + (size_t)((row + 8) & (T_ - 1)) * N + col;
            v0.x += b0[0]; v0.y += b0[1];
            v1.x += b1[0]; v1.y += b1[1];
            size_t i0 = (size_t)row * N + col;
            size_t i1 = (size_t)(row + 8) * N + col;
            uint32_t h, l;
            split2h(v0.x, v0.y, h, l);
            *(uint32_t*)&Chi[i0] = h; *(uint32_t*)&Clo[i0] = l;
            split2h(v1.x, v1.y, h, l);
            *(uint32_t*)&Chi[i1] = h; *(uint32_t*)&Clo[i1] = l;
        }
    }
}

// ---------------------------------------------------------------------------
// Flash attention: BQ=64, 128 threads (4 warps x 16 q-rows), 4 CTAs/SM.
// Q fp16 hi/lo, K/V/P single fp16. 64-token double-buffered stages.
// ---------------------------------------------------------------------------
#define A_ARR      9216               // bytes per array (64 rows * 144B)
#define A_STAGE    (2 * A_ARR)        // K, V per stage = 18432B
#define A_SMEM     (2 * A_STAGE)      // 36864B
#define SM_OFF     6.0f

extern __shared__ char attnsmem[];

__device__ __forceinline__ void attn_issue(
    uint32_t sbase, int s,
    const __half* K1, const __half* V1,
    size_t base, int t, int ldrow, int ldh)
{
    size_t grow = base + (size_t)(t * 64 + ldrow) * D_ + ldh * 32;
    uint32_t so = sbase + s * A_STAGE + ldrow * 144 + ldh * 64;
#pragma unroll
    for (int c = 0; c < 4; c++) {
        cp16(so + 0 * A_ARR + c * 16, K1 + grow + c * 8);
        cp16(so + 1 * A_ARR + c * 16, V1 + grow + c * 8);
    }
    asm volatile("cp.async.commit_group;" ::: "memory");
}

__global__ void __launch_bounds__(128, 4) attn_f16(
    const __half* __restrict__ Qh, const __half* __restrict__ Ql,
    const __half* __restrict__ K1, const __half* __restrict__ V1,
    __half* __restrict__ Ohi, __half* __restrict__ Olo)
{
    const int tid  = threadIdx.x;
    const int lane = tid & 31;
    const int wid  = tid >> 5;      // 0..3
    const int g    = lane >> 2;
    const int j    = lane & 3;

    const int q0 = blockIdx.x * 64;
    const int hh = blockIdx.y;
    const int bb = blockIdx.z;
    const size_t base = ((size_t)bb * T_) * D_ + (size_t)hh * HD_;

    const int ldrow = tid >> 1;     // 0..63
    const int ldh   = tid & 1;
    const uint32_t sbase = smem_u32(attnsmem);

    attn_issue(sbase, 0, K1, V1, base, 0, ldrow, ldh);

    // ---- Q fragments; fold in 0.125*log2(e), re-split to fp16 hi/lo ----
    uint32_t Qfh[4][4], Qfl[4][4];
    {
        const uint32_t* qh32 = (const uint32_t*)(Qh + base);
        const uint32_t* ql32 = (const uint32_t*)(Ql + base);
        int r0 = q0 + wid * 16 + g;
        const float SC = 0.18033688011112042f;
#pragma unroll
        for (int kf = 0; kf < 4; kf++) {
            int w0 = kf * 8 + j, w1 = kf * 8 + 4 + j;
            uint32_t rh[4], rl[4];
            rh[0] = qh32[(size_t)r0 * (D_ / 2) + w0];
            rh[1] = qh32[(size_t)(r0 + 8) * (D_ / 2) + w0];
            rh[2] = qh32[(size_t)r0 * (D_ / 2) + w1];
            rh[3] = qh32[(size_t)(r0 + 8) * (D_ / 2) + w1];
            rl[0] = ql32[(size_t)r0 * (D_ / 2) + w0];
            rl[1] = ql32[(size_t)(r0 + 8) * (D_ / 2) + w0];
            rl[2] = ql32[(size_t)r0 * (D_ / 2) + w1];
            rl[3] = ql32[(size_t)(r0 + 8) * (D_ / 2) + w1];
#pragma unroll
            for (int i = 0; i < 4; i++) {
                float2 a = __half22float2(*(__half2*)&rh[i]);
                float2 b = __half22float2(*(__half2*)&rl[i]);
                split2h((a.x + b.x) * SC, (a.y + b.y) * SC, Qfh[kf][i], Qfl[kf][i]);
            }
        }
    }

    const int lr8  = (lane & 7) + ((lane >> 3) & 1) * 8;
    const int lc16 = (lane >> 4) * 16;

    float oac[8][4];
#pragma unroll
    for (int nt = 0; nt < 8; nt++)
#pragma unroll
        for (int i = 0; i < 4; i++) oac[nt][i] = 0.f;
    float l0 = 0.f, l1 = 0.f;

    const int NTILE = T_ / 64;      // 32 stages of 64 tokens

    for (int t = 0; t < NTILE; t++) {
        const int s = t & 1;

        asm volatile("cp.async.wait_group 0;" ::: "memory");
        __syncthreads();

        if (t + 1 < NTILE)
            attn_issue(sbase, s ^ 1, K1, V1, base, t + 1, ldrow, ldh);

        const uint32_t kh_b = sbase + s * A_STAGE + 0 * A_ARR;
        const uint32_t vh_b = sbase + s * A_STAGE + 1 * A_ARR;

        float sac[8][4];
#pragma unroll
        for (int nt = 0; nt < 8; nt++)
#pragma unroll
            for (int i = 0; i < 4; i++) sac[nt][i] = 0.f;

#pragma unroll
        for (int kf = 0; kf < 4; kf++) {
#pragma unroll
            for (int np = 0; np < 4; np++) {
                uint32_t off = (np * 16 + lr8) * 144 + kf * 32 + lc16;
                uint32_t bh[4];
                ldsm4(bh, kh_b + off);
                uint32_t bA[2] = { bh[0], bh[2] }, bB[2] = { bh[1], bh[3] };
                mma16816(sac[np * 2],     Qfh[kf], bA);
                mma16816(sac[np * 2],     Qfl[kf], bA);
                mma16816(sac[np * 2 + 1], Qfh[kf], bB);
                mma16816(sac[np * 2 + 1], Qfl[kf], bB);
            }
        }

        // fixed-offset softmax: p = 2^(sac - 6)
        float rs0 = 0.f, rs1 = 0.f;
#pragma unroll
        for (int nt = 0; nt < 8; nt++) {
            sac[nt][0] = ex2(sac[nt][0] - SM_OFF);
            sac[nt][1] = ex2(sac[nt][1] - SM_OFF);
            sac[nt][2] = ex2(sac[nt][2] - SM_OFF);
            sac[nt][3] = ex2(sac[nt][3] - SM_OFF);
            rs0 += sac[nt][0] + sac[nt][1];
            rs1 += sac[nt][2] + sac[nt][3];
        }
        l0 += rs0;
        l1 += rs1;

        // O += P V (P single fp16)
#pragma unroll
        for (int kf = 0; kf < 4; kf++) {
            uint32_t ph[4];
            ph[0] = cvt2h(sac[2 * kf][0],     sac[2 * kf][1]);
            ph[1] = cvt2h(sac[2 * kf][2],     sac[2 * kf][3]);
            ph[2] = cvt2h(sac[2 * kf + 1][0], sac[2 * kf + 1][1]);
            ph[3] = cvt2h(sac[2 * kf + 1][2], sac[2 * kf + 1][3]);
#pragma unroll
            for (int np = 0; np < 4; np++) {
                uint32_t off = (kf * 16 + lr8) * 144 + np * 32 + lc16;
                uint32_t vh[4];
                ldsm4t(vh, vh_b + off);
                uint32_t vA[2] = { vh[0], vh[1] }, vB[2] = { vh[2], vh[3] };
                mma16816(oac[np * 2],     ph, vA);
                mma16816(oac[np * 2 + 1], ph, vB);
            }
        }
    }

#pragma unroll
    for (int off = 1; off <= 2; off <<= 1) {
        l0 += __shfl_xor_sync(0xffffffffu, l0, off);
        l1 += __shfl_xor_sync(0xffffffffu, l1, off);
    }
    float inv0 = 1.f / l0, inv1 = 1.f / l1;
    int row = q0 + wid * 16 + g;
    uint32_t* oh32 = (uint32_t*)(Ohi + base);
    uint32_t* ol32 = (uint32_t*)(Olo + base);
#pragma unroll
    for (int nt = 0; nt < 8; nt++) {
        int w = nt * 4 + j;
        uint32_t h, l;
        split2h(oac[nt][0] * inv0, oac[nt][1] * inv0, h, l);
        oh32[(size_t)row * (D_ / 2) + w] = h;
        ol32[(size_t)row * (D_ / 2) + w] = l;
        split2h(oac[nt][2] * inv1, oac[nt][3] * inv1, h, l);
        oh32[(size_t)(row + 8) * (D_ / 2) + w] = h;
        ol32[(size_t)(row + 8) * (D_ / 2) + w] = l;
    }
}

// ---------------------------------------------------------------------------
// Final-layer Wp on last tokens only.
// ---------------------------------------------------------------------------
__global__ void __launch_bounds__(256) hlast_kernel(
    const __half* __restrict__ Oh, const __half* __restrict__ Ol,
    const float* __restrict__ Wp3, float* __restrict__ hlast)
{
    __shared__ float os[D_];
    const int b = blockIdx.x;
    const size_t obase = ((size_t)b * T_ + (T_ - 1)) * D_;
    for (int d = threadIdx.x; d < D_; d += 256)
        os[d] = __half2float(Oh[obase + d]) + __half2float(Ol[obase + d]);
    __syncthreads();

    const float sD = 0.04419417382415922f;
    for (int od = threadIdx.x; od < D_; od += 256) {
        const float* w = Wp3 + (size_t)od * D_;
        float a0 = 0.f, a1 = 0.f, a2 = 0.f, a3 = 0.f;
        for (int k = 0; k < D_; k += 4) {
            float4 wv = *(const float4*)(w + k);
            a0 += wv.x * os[k];
            a1 += wv.y * os[k + 1];
            a2 += wv.z * os[k + 2];
            a3 += wv.w * os[k + 3];
        }
        hlast[b * D_ + od] = (a0 + a1 + a2 + a3) * sD;
    }
}

// ---------------------------------------------------------------------------
__global__ void __launch_bounds__(256) readout_kernel(
    const float* __restrict__ hlast, const float* __restrict__ R,
    float* __restrict__ out)
{
    __shared__ float hs[B_][D_];
    for (int i = threadIdx.x; i < B_ * D_; i += 256) {
        int b = i >> 9, d = i & 511;
        hs[b][d] = hlast[b * D_ + d];
    }
    __syncthreads();

    int v = blockIdx.x * 256 + threadIdx.x;
    float a0 = 0.f, a1 = 0.f, a2 = 0.f, a3 = 0.f;
    const float* r = R + (size_t)v * D_;
    for (int d = 0; d < D_; d += 4) {
        float4 rv = *(const float4*)(r + d);
        a0 += rv.x * hs[0][d] + rv.y * hs[0][d + 1] + rv.z * hs[0][d + 2] + rv.w * hs[0][d + 3];
        a1 += rv.x * hs[1][d] + rv.y * hs[1][d + 1] + rv.z * hs[1][d + 2] + rv.w * hs[1][d + 3];
        a2 += rv.x * hs[2][d] + rv.y * hs[2][d + 1] + rv.z * hs[2][d + 2] + rv.w * hs[2][d + 3];
        a3 += rv.x * hs[3][d] + rv.y * hs[3][d + 1] + rv.z * hs[3][d + 2] + rv.w * hs[3][d + 3];
    }
    const float sc = 0.04419417382415922f;
    out[0 * V_ + v] = a0 * sc;
    out[1 * V_ + v] = a1 * sc;
    out[2 * V_ + v] = a2 * sc;
    out[3 * V_ + v] = a3 * sc;
}

// ---------------------------------------------------------------------------
extern "C" void kernel_launch(void* const* d_in, const int* in_sizes, int n_in,
                              void* d_out, int out_size)
{
    const float* x  = (const float*)d_in[0];
    const float* te = (const float*)d_in[1];
    const float* pe = (const float*)d_in[2];
    const float* Wk = (const float*)d_in[3];
    const float* Wq = (const float*)d_in[4];
    const float* Wv = (const float*)d_in[5];
    const float* Wp = (const float*)d_in[6];
    const float* ro = (const float*)d_in[7];
    float* out = (float*)d_out;

    __half *hh, *hl, *qh, *ql, *k1, *v1, *oh, *ol;
    __half *te1, *wq1, *wk1, *wv1, *wpT, *uq, *uk, *uv;
    float* hlast;
    cudaGetSymbolAddress((void**)&hh,  g_hh);  cudaGetSymbolAddress((void**)&hl, g_hl);
    cudaGetSymbolAddress((void**)&qh,  g_qh);  cudaGetSymbolAddress((void**)&ql, g_ql);
    cudaGetSymbolAddress((void**)&k1,  g_k1);
    cudaGetSymbolAddress((void**)&v1,  g_v1);
    cudaGetSymbolAddress((void**)&oh,  g_oh);  cudaGetSymbolAddress((void**)&ol, g_ol);
    cudaGetSymbolAddress((void**)&te1, g_te1);
    cudaGetSymbolAddress((void**)&wq1, g_wq1);
    cudaGetSymbolAddress((void**)&wk1, g_wk1);
    cudaGetSymbolAddress((void**)&wv1, g_wv1);
    cudaGetSymbolAddress((void**)&wpT, g_wpT);
    cudaGetSymbolAddress((void**)&uq,  g_uq);
    cudaGetSymbolAddress((void**)&uk,  g_uk);
    cudaGetSymbolAddress((void**)&uv,  g_uv);
    cudaGetSymbolAddress((void**)&hlast, g_hlast);

    const float sV = 0.022097086912079608f;  // 1/sqrt(2048)
    const float sD = 0.04419417382415922f;   // 1/sqrt(512)

    {
        int n4 = (D_ * V_) / 4;
        tohalf_kernel<<<(n4 + 255) / 256, 256>>>((const float4*)te, (uint2*)te1, n4);
        n4 = DD_ / 4;
        tohalf_kernel<<<(n4 + 255) / 256, 256>>>((const float4*)Wq, (uint2*)wq1, n4);
        tohalf_kernel<<<(n4 + 255) / 256, 256>>>((const float4*)Wk, (uint2*)wk1, n4);
        tohalf_kernel<<<(n4 + 255) / 256, 256>>>((const float4*)Wv, (uint2*)wv1, n4);
        transpose_kernel<<<dim3(16, 16, 3), 256>>>(Wp, wpT);
        gemm_combine<<<dim3(4, 4, 9), 256>>>(Wq, Wk, Wv, wpT, uq, uk, uv);
    }

    dim3 qkvgrid(D_ / 128, (B_ * T_) / 128, 3);

    // embed: h = x @ TE^T / sqrt(V) + pos
    gemm_nt_f32a<<<dim3(D_ / 128, (B_ * T_) / 128), 256>>>(
        x, te1, hh, hl, pe, B_ * T_, D_, V_, sV);

    for (int l = 0; l < L_; l++) {
        if (l == 0) {
            gemm_qkv<<<qkvgrid, 256>>>(hh, hl, wq1, wk1, wv1,
                                       qh, ql, k1, v1, sD);
        } else {
            size_t uo = (size_t)(l - 1) * DD_;
            gemm_qkv<<<qkvgrid, 256>>>(oh, ol, uq + uo, uk + uo, uv + uo,
                                       qh, ql, k1, v1, sD * sD);
        }

        attn_f16<<<dim3(T_ / 64, H_, B_), 128, A_SMEM>>>(qh, ql, k1, v1, oh, ol);
    }

    hlast_kernel<<<B_, 256>>>(oh, ol, Wp + (size_t)3 * DD_, hlast);
    readout_kernel<<<V_ / 256, 256>>>(hlast, ro, out);
}

// round 17
// speedup vs baseline: 1.0183x; 1.0183x over previous
#include <cuda_runtime.h>
#include <cuda_fp16.h>
#include <math.h>
#include <stdint.h>

#define B_  4
#define T_  2048
#define V_  2048
#define D_  512
#define H_  8
#define L_  4
#define HD_ 64
#define NT_ (B_ * T_ * D_)   // 4M elems
#define DD_ (D_ * D_)

// ---- global scratch (no allocation allowed) ----
__device__ __align__(16) __half g_hh[NT_], g_hl[NT_];
__device__ __align__(16) __half g_qh[NT_], g_ql[NT_];
__device__ __align__(16) __half g_k1[NT_];
__device__ __align__(16) __half g_v1[NT_];
__device__ __align__(16) __half g_oh[NT_], g_ol[NT_];
__device__ __align__(16) __half g_te1[D_ * V_];
__device__ __align__(16) __half g_wq1[DD_];            // layer-0 weights only
__device__ __align__(16) __half g_wk1[DD_];
__device__ __align__(16) __half g_wv1[DD_];
__device__ __align__(16) __half g_wpT[3 * DD_];        // Wp^T fp16, layers 0..2
__device__ __align__(16) __half g_uq[3 * DD_];         // folded W_{l+1}·Wp_l
__device__ __align__(16) __half g_uk[3 * DD_];
__device__ __align__(16) __half g_uv[3 * DD_];
__device__ __align__(16) float  g_hlast[B_ * D_];

// ---------------------------------------------------------------------------
__device__ __forceinline__ void split2h(float x, float y, uint32_t& h, uint32_t& l)
{
    __half2 hv = __float22half2_rn(make_float2(x, y));
    float2 hf = __half22float2(hv);
    __half2 lv = __float22half2_rn(make_float2(x - hf.x, y - hf.y));
    h = *reinterpret_cast<uint32_t*>(&hv);
    l = *reinterpret_cast<uint32_t*>(&lv);
}

__device__ __forceinline__ uint32_t cvt2h(float x, float y)
{
    __half2 v = __float22half2_rn(make_float2(x, y));
    return *reinterpret_cast<uint32_t*>(&v);
}

__device__ __forceinline__ float ex2(float x)
{
    float y;
    asm("ex2.approx.f32 %0, %1;" : "=f"(y) : "f"(x));
    return y;
}

__device__ __forceinline__ void mma16816(float* d, const uint32_t* a, const uint32_t* b)
{
    asm volatile(
        "mma.sync.aligned.m16n8k16.row.col.f32.f16.f16.f32 "
        "{%0,%1,%2,%3}, {%4,%5,%6,%7}, {%8,%9}, {%0,%1,%2,%3};\n"
        : "+f"(d[0]), "+f"(d[1]), "+f"(d[2]), "+f"(d[3])
        : "r"(a[0]), "r"(a[1]), "r"(a[2]), "r"(a[3]), "r"(b[0]), "r"(b[1]));
}

__device__ __forceinline__ void ldsm4(uint32_t* r, uint32_t addr)
{
    asm volatile("ldmatrix.sync.aligned.m8n8.x4.shared.b16 {%0,%1,%2,%3}, [%4];"
                 : "=r"(r[0]), "=r"(r[1]), "=r"(r[2]), "=r"(r[3]) : "r"(addr));
}
__device__ __forceinline__ void ldsm4t(uint32_t* r, uint32_t addr)
{
    asm volatile("ldmatrix.sync.aligned.m8n8.x4.trans.shared.b16 {%0,%1,%2,%3}, [%4];"
                 : "=r"(r[0]), "=r"(r[1]), "=r"(r[2]), "=r"(r[3]) : "r"(addr));
}

__device__ __forceinline__ uint32_t smem_u32(const void* p)
{
    uint32_t a;
    asm("{ .reg .u64 t; cvta.to.shared.u64 t, %1; cvt.u32.u64 %0, t; }" : "=r"(a) : "l"(p));
    return a;
}

__device__ __forceinline__ void cp16(uint32_t saddr, const void* gaddr)
{
    asm volatile("cp.async.cg.shared.global [%0], [%1], 16;" :: "r"(saddr), "l"(gaddr));
}

// ---------------------------------------------------------------------------
__global__ void __launch_bounds__(256) tohalf_kernel(
    const float4* __restrict__ src, uint2* __restrict__ dst, int n4)
{
    int i = blockIdx.x * 256 + threadIdx.x;
    if (i < n4) {
        float4 f = src[i];
        dst[i] = make_uint2(cvt2h(f.x, f.y), cvt2h(f.z, f.w));
    }
}

// ---------------------------------------------------------------------------
// Transpose Wp (fp32 [D,D]) -> wpT (fp16 [D,D]), layers 0..2.
// ---------------------------------------------------------------------------
__global__ void __launch_bounds__(256) transpose_kernel(
    const float* __restrict__ Wp, __half* __restrict__ wpT)
{
    __shared__ float tile[32][33];
    const int l  = blockIdx.z;
    const int x0 = blockIdx.x * 32;
    const int y0 = blockIdx.y * 32;
    const float* S = Wp + (size_t)l * DD_;
    __half* Dp = wpT + (size_t)l * DD_;
    const int tx = threadIdx.x & 31;
    const int ty = threadIdx.x >> 5;
#pragma unroll
    for (int i = ty; i < 32; i += 8)
        tile[i][tx] = S[(size_t)(y0 + i) * D_ + x0 + tx];
    __syncthreads();
#pragma unroll
    for (int i = ty; i < 32; i += 8)
        Dp[(size_t)(x0 + i) * D_ + y0 + tx] = __float2half(tile[tx][i]);
}

#define GST 24          // smem row stride in fp16 (48 bytes)
#define GBUF 3072       // 128 * 24 fp16 per (part, stage)

// ---------------------------------------------------------------------------
// Weight-combine GEMM: U_x,l = W_x,{l+1} @ Wp_l
// ---------------------------------------------------------------------------
__global__ void __launch_bounds__(256) gemm_combine(
    const float* __restrict__ Wq, const float* __restrict__ Wk,
    const float* __restrict__ Wv, const __half* __restrict__ wpT,
    __half* __restrict__ Uq, __half* __restrict__ Uk, __half* __restrict__ Uv)
{
    __shared__ __align__(16) __half sm[2][3][GBUF];

    const int z = blockIdx.z;
    const int l = z / 3, xx = z % 3;
    const float* Af = ((xx == 0) ? Wq : (xx == 1) ? Wk : Wv) + (size_t)(l + 1) * DD_;
    const __half* Bm = wpT + (size_t)l * DD_;
    __half* C = ((xx == 0) ? Uq : (xx == 1) ? Uk : Uv) + (size_t)l * DD_;
    const int N = D_, K = D_;

    const int tid  = threadIdx.x;
    const int lane = tid & 31;
    const int wid  = tid >> 5;
    const int wm   = (wid & 3) * 32;
    const int wn   = (wid >> 2) * 64;
    const int bm   = blockIdx.y * 128;
    const int bn   = blockIdx.x * 128;
    const int g    = lane >> 2;
    const int j    = lane & 3;

    const int lrow  = tid >> 1;
    const int lhalf = tid & 1;
    const float* pAf = Af + (size_t)(bm + lrow) * K + lhalf * 8;
    const __half* pB = Bm + (size_t)(bn + lrow) * K + lhalf * 8;
    const int sidx = lrow * GST + lhalf * 8;

    const int lr8  = (lane & 7) + ((lane >> 3) & 1) * 8;
    const int lc16 = (lane >> 4) * 16;
    const uint32_t smbase = smem_u32(&sm[0][0][0]);
    uint32_t offA[2], offB[4];
#pragma unroll
    for (int mt = 0; mt < 2; mt++) offA[mt] = (wm + mt * 16 + lr8) * 48 + lc16;
#pragma unroll
    for (int np = 0; np < 4; np++) offB[np] = (wn + np * 16 + lr8) * 48 + lc16;

    float acc[2][8][4];
#pragma unroll
    for (int mt = 0; mt < 2; mt++)
#pragma unroll
        for (int nt = 0; nt < 8; nt++)
#pragma unroll
            for (int i = 0; i < 4; i++) acc[mt][nt][i] = 0.f;

    const int KT = K >> 4;

    {
        float4 f0 = *(const float4*)(pAf);
        float4 f1 = *(const float4*)(pAf + 4);
        uint32_t h[4], l4[4];
        split2h(f0.x, f0.y, h[0], l4[0]);
        split2h(f0.z, f0.w, h[1], l4[1]);
        split2h(f1.x, f1.y, h[2], l4[2]);
        split2h(f1.z, f1.w, h[3], l4[3]);
        *(uint4*)&sm[0][0][sidx] = make_uint4(h[0], h[1], h[2], h[3]);
        *(uint4*)&sm[0][1][sidx] = make_uint4(l4[0], l4[1], l4[2], l4[3]);
        *(uint4*)&sm[0][2][sidx] = *(const uint4*)pB;
    }
    __syncthreads();

    for (int ks = 0; ks < KT; ks++) {
        const int cur = ks & 1, nxt = cur ^ 1;

        float4 rf0, rf1;
        uint4 rb;
        if (ks + 1 < KT) {
            int k0 = (ks + 1) << 4;
            rf0 = *(const float4*)(pAf + k0);
            rf1 = *(const float4*)(pAf + k0 + 4);
            rb  = *(const uint4*)(pB + k0);
        }

        const uint32_t sb = smbase + cur * (3 * GBUF * 2);
        uint32_t fah[2][4], fal[2][4];
#pragma unroll
        for (int mt = 0; mt < 2; mt++) {
            ldsm4(fah[mt], sb + 0 * (GBUF * 2) + offA[mt]);
            ldsm4(fal[mt], sb + 1 * (GBUF * 2) + offA[mt]);
        }
#pragma unroll
        for (int np = 0; np < 4; np++) {
            uint32_t bh[4];
            ldsm4(bh, sb + 2 * (GBUF * 2) + offB[np]);
            uint32_t bA[2] = { bh[0], bh[2] }, bB[2] = { bh[1], bh[3] };
#pragma unroll
            for (int mt = 0; mt < 2; mt++) {
                mma16816(acc[mt][np * 2],     fah[mt], bA);
                mma16816(acc[mt][np * 2],     fal[mt], bA);
                mma16816(acc[mt][np * 2 + 1], fah[mt], bB);
                mma16816(acc[mt][np * 2 + 1], fal[mt], bB);
            }
        }

        if (ks + 1 < KT) {
            uint32_t h[4], l4[4];
            split2h(rf0.x, rf0.y, h[0], l4[0]);
            split2h(rf0.z, rf0.w, h[1], l4[1]);
            split2h(rf1.x, rf1.y, h[2], l4[2]);
            split2h(rf1.z, rf1.w, h[3], l4[3]);
            *(uint4*)&sm[nxt][0][sidx] = make_uint4(h[0], h[1], h[2], h[3]);
            *(uint4*)&sm[nxt][1][sidx] = make_uint4(l4[0], l4[1], l4[2], l4[3]);
            *(uint4*)&sm[nxt][2][sidx] = rb;
        }
        __syncthreads();
    }

#pragma unroll
    for (int mt = 0; mt < 2; mt++) {
#pragma unroll
        for (int nt = 0; nt < 8; nt++) {
            int row = bm + wm + mt * 16 + g;
            int col = bn + wn + nt * 8 + j * 2;
            size_t i0 = (size_t)row * N + col;
            size_t i1 = (size_t)(row + 8) * N + col;
            *(uint32_t*)&C[i0] = cvt2h(acc[mt][nt][0], acc[mt][nt][1]);
            *(uint32_t*)&C[i1] = cvt2h(acc[mt][nt][2], acc[mt][nt][3]);
        }
    }
}

// ---------------------------------------------------------------------------
// Fused QKV GEMM: z=0 -> q (hi/lo, 2-term), z=1 -> k (single out, 1-term),
// z=2 -> v (single out, 2-term).
// ---------------------------------------------------------------------------
__global__ void __launch_bounds__(256, 2) gemm_qkv(
    const __half* __restrict__ Ah, const __half* __restrict__ Al,
    const __half* __restrict__ W0, const __half* __restrict__ W1,
    const __half* __restrict__ W2,
    __half* __restrict__ Qhi, __half* __restrict__ Qlo,
    __half* __restrict__ K1, __half* __restrict__ V1,
    float alpha)
{
    __shared__ __align__(16) __half sm[2][3][GBUF];

    const int z = blockIdx.z;
    const __half* Bm = (z == 0) ? W0 : (z == 1) ? W1 : W2;
    __half* Chi = (z == 0) ? Qhi : (z == 1) ? K1 : V1;
    __half* Clo = (z == 0) ? Qlo : nullptr;
    const bool useAl = (z != 1);   // K projection: drop the A-lo term
    const int N = D_, K = D_;

    const int tid  = threadIdx.x;
    const int lane = tid & 31;
    const int wid  = tid >> 5;
    const int wm   = (wid & 3) * 32;
    const int wn   = (wid >> 2) * 64;
    const int bm   = blockIdx.y * 128;
    const int bn   = blockIdx.x * 128;
    const int g    = lane >> 2;
    const int j    = lane & 3;

    const int lrow  = tid >> 1;
    const int lhalf = tid & 1;
    const __half* pAh = Ah + (size_t)(bm + lrow) * K + lhalf * 8;
    const __half* pAl = Al + (size_t)(bm + lrow) * K + lhalf * 8;
    const __half* pB  = Bm + (size_t)(bn + lrow) * K + lhalf * 8;
    const int sidx = lrow * GST + lhalf * 8;

    const int lr8  = (lane & 7) + ((lane >> 3) & 1) * 8;
    const int lc16 = (lane >> 4) * 16;
    const uint32_t smbase = smem_u32(&sm[0][0][0]);
    uint32_t offA[2], offB[4];
#pragma unroll
    for (int mt = 0; mt < 2; mt++) offA[mt] = (wm + mt * 16 + lr8) * 48 + lc16;
#pragma unroll
    for (int np = 0; np < 4; np++) offB[np] = (wn + np * 16 + lr8) * 48 + lc16;

    float acc[2][8][4];
#pragma unroll
    for (int mt = 0; mt < 2; mt++)
#pragma unroll
        for (int nt = 0; nt < 8; nt++)
#pragma unroll
            for (int i = 0; i < 4; i++) acc[mt][nt][i] = 0.f;

    const int KT = K >> 4;

    {
        *(uint4*)&sm[0][0][sidx] = *(const uint4*)pAh;
        *(uint4*)&sm[0][1][sidx] = *(const uint4*)pAl;
        *(uint4*)&sm[0][2][sidx] = *(const uint4*)pB;
    }
    __syncthreads();

    for (int ks = 0; ks < KT; ks++) {
        const int cur = ks & 1, nxt = cur ^ 1;

        uint4 rah, ral, rb;
        if (ks + 1 < KT) {
            int k0 = (ks + 1) << 4;
            rah = *(const uint4*)(pAh + k0);
            ral = *(const uint4*)(pAl + k0);
            rb  = *(const uint4*)(pB + k0);
        }

        const uint32_t sb = smbase + cur * (3 * GBUF * 2);
        uint32_t fah[2][4], fal[2][4];
#pragma unroll
        for (int mt = 0; mt < 2; mt++) {
            ldsm4(fah[mt], sb + 0 * (GBUF * 2) + offA[mt]);
            ldsm4(fal[mt], sb + 1 * (GBUF * 2) + offA[mt]);
        }
#pragma unroll
        for (int np = 0; np < 4; np++) {
            uint32_t bh[4];
            ldsm4(bh, sb + 2 * (GBUF * 2) + offB[np]);
            uint32_t bA[2] = { bh[0], bh[2] }, bB[2] = { bh[1], bh[3] };
#pragma unroll
            for (int mt = 0; mt < 2; mt++) {
                mma16816(acc[mt][np * 2],     fah[mt], bA);
                mma16816(acc[mt][np * 2 + 1], fah[mt], bB);
                if (useAl) {
                    mma16816(acc[mt][np * 2],     fal[mt], bA);
                    mma16816(acc[mt][np * 2 + 1], fal[mt], bB);
                }
            }
        }

        if (ks + 1 < KT) {
            *(uint4*)&sm[nxt][0][sidx] = rah;
            *(uint4*)&sm[nxt][1][sidx] = ral;
            *(uint4*)&sm[nxt][2][sidx] = rb;
        }
        __syncthreads();
    }

#pragma unroll
    for (int mt = 0; mt < 2; mt++) {
#pragma unroll
        for (int nt = 0; nt < 8; nt++) {
            int row = bm + wm + mt * 16 + g;
            int col = bn + wn + nt * 8 + j * 2;
            float2 v0 = make_float2(acc[mt][nt][0] * alpha, acc[mt][nt][1] * alpha);
            float2 v1 = make_float2(acc[mt][nt][2] * alpha, acc[mt][nt][3] * alpha);
            size_t i0 = (size_t)row * N + col;
            size_t i1 = (size_t)(row + 8) * N + col;
            if (Clo) {
                uint32_t h, l;
                split2h(v0.x, v0.y, h, l);
                *(uint32_t*)&Chi[i0] = h; *(uint32_t*)&Clo[i0] = l;
                split2h(v1.x, v1.y, h, l);
                *(uint32_t*)&Chi[i1] = h; *(uint32_t*)&Clo[i1] = l;
            } else {
                *(uint32_t*)&Chi[i0] = cvt2h(v0.x, v0.y);
                *(uint32_t*)&Chi[i1] = cvt2h(v1.x, v1.y);
            }
        }
    }
}

// ---------------------------------------------------------------------------
// Embed GEMM: A fp32 (x) split inline; B = te single fp16.
// ---------------------------------------------------------------------------
__global__ void __launch_bounds__(256, 2) gemm_nt_f32a(
    const float* __restrict__ Af, const __half* __restrict__ Bm,
    __half* __restrict__ Chi, __half* __restrict__ Clo,
    const float* __restrict__ bias, int M, int N, int K, float alpha)
{
    __shared__ __align__(16) __half sm[2][3][GBUF];

    const int tid  = threadIdx.x;
    const int lane = tid & 31;
    const int wid  = tid >> 5;
    const int wm   = (wid & 3) * 32;
    const int wn   = (wid >> 2) * 64;
    const int bm   = blockIdx.y * 128;
    const int bn   = blockIdx.x * 128;
    const int g    = lane >> 2;
    const int j    = lane & 3;

    const int lrow  = tid >> 1;
    const int lhalf = tid & 1;
    const float* pAf = Af + (size_t)(bm + lrow) * K + lhalf * 8;
    const __half* pB = Bm + (size_t)(bn + lrow) * K + lhalf * 8;
    const int sidx = lrow * GST + lhalf * 8;

    const int lr8  = (lane & 7) + ((lane >> 3) & 1) * 8;
    const int lc16 = (lane >> 4) * 16;
    const uint32_t smbase = smem_u32(&sm[0][0][0]);
    uint32_t offA[2], offB[4];
#pragma unroll
    for (int mt = 0; mt < 2; mt++) offA[mt] = (wm + mt * 16 + lr8) * 48 + lc16;
#pragma unroll
    for (int np = 0; np < 4; np++) offB[np] = (wn + np * 16 + lr8) * 48 + lc16;

    float acc[2][8][4];
#pragma unroll
    for (int mt = 0; mt < 2; mt++)
#pragma unroll
        for (int nt = 0; nt < 8; nt++)
#pragma unroll
            for (int i = 0; i < 4; i++) acc[mt][nt][i] = 0.f;

    const int KT = K >> 4;

    {
        float4 f0 = *(const float4*)(pAf);
        float4 f1 = *(const float4*)(pAf + 4);
        uint32_t h[4], l[4];
        split2h(f0.x, f0.y, h[0], l[0]);
        split2h(f0.z, f0.w, h[1], l[1]);
        split2h(f1.x, f1.y, h[2], l[2]);
        split2h(f1.z, f1.w, h[3], l[3]);
        *(uint4*)&sm[0][0][sidx] = make_uint4(h[0], h[1], h[2], h[3]);
        *(uint4*)&sm[0][1][sidx] = make_uint4(l[0], l[1], l[2], l[3]);
        *(uint4*)&sm[0][2][sidx] = *(const uint4*)pB;
    }
    __syncthreads();

    for (int ks = 0; ks < KT; ks++) {
        const int cur = ks & 1, nxt = cur ^ 1;

        float4 rf0, rf1;
        uint4 rb;
        if (ks + 1 < KT) {
            int k0 = (ks + 1) << 4;
            rf0 = *(const float4*)(pAf + k0);
            rf1 = *(const float4*)(pAf + k0 + 4);
            rb  = *(const uint4*)(pB + k0);
        }

        const uint32_t sb = smbase + cur * (3 * GBUF * 2);
        uint32_t fah[2][4], fal[2][4];
#pragma unroll
        for (int mt = 0; mt < 2; mt++) {
            ldsm4(fah[mt], sb + 0 * (GBUF * 2) + offA[mt]);
            ldsm4(fal[mt], sb + 1 * (GBUF * 2) + offA[mt]);
        }
#pragma unroll
        for (int np = 0; np < 4; np++) {
            uint32_t bh[4];
            ldsm4(bh, sb + 2 * (GBUF * 2) + offB[np]);
            uint32_t bA[2] = { bh[0], bh[2] }, bB[2] = { bh[1], bh[3] };
#pragma unroll
            for (int mt = 0; mt < 2; mt++) {
                mma16816(acc[mt][np * 2],     fah[mt], bA);
                mma16816(acc[mt][np * 2],     fal[mt], bA);
                mma16816(acc[mt][np * 2 + 1], fah[mt], bB);
                mma16816(acc[mt][np * 2 + 1], fal[mt], bB);
            }
        }

        if (ks + 1 < KT) {
            uint32_t h[4], l[4];
            split2h(rf0.x, rf0.y, h[0], l[0]);
            split2h(rf0.z, rf0.w, h[1], l[1]);
            split2h(rf1.x, rf1.y, h[2], l[2]);
            split2h(rf1.z, rf1.w, h[3], l[3]);
            *(uint4*)&sm[nxt][0][sidx] = make_uint4(h[0], h[1], h[2], h[3]);
            *(uint4*)&sm[nxt][1][sidx] = make_uint4(l[0], l[1], l[2], l[3]);
            *(uint4*)&sm[nxt][2][sidx] = rb;
        }
        __syncthreads();
    }

#pragma unroll
    for (int mt = 0; mt < 2; mt++) {
#pragma unroll
        for (int nt = 0; nt < 8; nt++) {
            int row = bm + wm + mt * 16 + g;
            int col = bn + wn + nt * 8 + j * 2;
            float2 v0 = make_float2(acc[mt][nt][0] * alpha, acc[mt][nt][1] * alpha);
            float2 v1 = make_float2(acc[mt][nt][2] * alpha, acc[mt][nt][3] * alpha);
            const float* b0 = bias + (size_t)(row & (T_ - 1)) * N + col;
            const float* b1 = bias + (size_t)((row + 8) & (T_ - 1)) * N + col;
            v0.x += b0[0]; v0.y += b0[1];
            v1.x += b1[0]; v1.y += b1[1];
            size_t i0 = (size_t)row * N + col;
            size_t i1 = (size_t)(row + 8) * N + col;
            uint32_t h, l;
            split2h(v0.x, v0.y, h, l);
            *(uint32_t*)&Chi[i0] = h; *(uint32_t*)&Clo[i0] = l;
            split2h(v1.x, v1.y, h, l);
            *(uint32_t*)&Chi[i1] = h; *(uint32_t*)&Clo[i1] = l;
        }
    }
}

// ---------------------------------------------------------------------------
// Flash attention (R15 shape): BQ=128, 256 threads, 2 CTAs/SM.
// Q fp16 hi/lo, K/V/P single fp16. 128-token double-buffered stages.
// ---------------------------------------------------------------------------
#define A_ARR      18432              // bytes per array (128 rows * 144B)
#define A_STAGE    (2 * A_ARR)        // K, V per stage = 36864B
#define A_SMEM     (2 * A_STAGE)      // 73728B
#define SM_OFF     6.0f

extern __shared__ char attnsmem[];

__device__ __forceinline__ void attn_issue(
    uint32_t sbase, int s,
    const __half* K1, const __half* V1,
    size_t base, int t, int ldrow, int ldh)
{
    size_t grow = base + (size_t)(t * 128 + ldrow) * D_ + ldh * 32;
    uint32_t so = sbase + s * A_STAGE + ldrow * 144 + ldh * 64;
#pragma unroll
    for (int c = 0; c < 4; c++) {
        cp16(so + 0 * A_ARR + c * 16, K1 + grow + c * 8);
        cp16(so + 1 * A_ARR + c * 16, V1 + grow + c * 8);
    }
    asm volatile("cp.async.commit_group;" ::: "memory");
}

__global__ void __launch_bounds__(256, 2) attn_f16(
    const __half* __restrict__ Qh, const __half* __restrict__ Ql,
    const __half* __restrict__ K1, const __half* __restrict__ V1,
    __half* __restrict__ Ohi, __half* __restrict__ Olo)
{
    const int tid  = threadIdx.x;
    const int lane = tid & 31;
    const int wid  = tid >> 5;
    const int g    = lane >> 2;
    const int j    = lane & 3;

    const int q0 = blockIdx.x * 128;
    const int hh = blockIdx.y;
    const int bb = blockIdx.z;
    const size_t base = ((size_t)bb * T_) * D_ + (size_t)hh * HD_;

    const int ldrow = tid >> 1;
    const int ldh   = tid & 1;
    const uint32_t sbase = smem_u32(attnsmem);

    attn_issue(sbase, 0, K1, V1, base, 0, ldrow, ldh);

    uint32_t Qfh[4][4], Qfl[4][4];
    {
        const uint32_t* qh32 = (const uint32_t*)(Qh + base);
        const uint32_t* ql32 = (const uint32_t*)(Ql + base);
        int r0 = q0 + wid * 16 + g;
        const float SC = 0.18033688011112042f;
#pragma unroll
        for (int kf = 0; kf < 4; kf++) {
            int w0 = kf * 8 + j, w1 = kf * 8 + 4 + j;
            uint32_t rh[4], rl[4];
            rh[0] = qh32[(size_t)r0 * (D_ / 2) + w0];
            rh[1] = qh32[(size_t)(r0 + 8) * (D_ / 2) + w0];
            rh[2] = qh32[(size_t)r0 * (D_ / 2) + w1];
            rh[3] = qh32[(size_t)(r0 + 8) * (D_ / 2) + w1];
            rl[0] = ql32[(size_t)r0 * (D_ / 2) + w0];
            rl[1] = ql32[(size_t)(r0 + 8) * (D_ / 2) + w0];
            rl[2] = ql32[(size_t)r0 * (D_ / 2) + w1];
            rl[3] = ql32[(size_t)(r0 + 8) * (D_ / 2) + w1];
#pragma unroll
            for (int i = 0; i < 4; i++) {
                float2 a = __half22float2(*(__half2*)&rh[i]);
                float2 b = __half22float2(*(__half2*)&rl[i]);
                split2h((a.x + b.x) * SC, (a.y + b.y) * SC, Qfh[kf][i], Qfl[kf][i]);
            }
        }
    }

    const int lr8  = (lane & 7) + ((lane >> 3) & 1) * 8;
    const int lc16 = (lane >> 4) * 16;

    float oac[8][4];
#pragma unroll
    for (int nt = 0; nt < 8; nt++)
#pragma unroll
        for (int i = 0; i < 4; i++) oac[nt][i] = 0.f;
    float l0 = 0.f, l1 = 0.f;

    const int NTILE = T_ / 128;

    for (int t = 0; t < NTILE; t++) {
        const int s = t & 1;

        asm volatile("cp.async.wait_group 0;" ::: "memory");
        __syncthreads();

        if (t + 1 < NTILE)
            attn_issue(sbase, s ^ 1, K1, V1, base, t + 1, ldrow, ldh);

        const uint32_t kst = sbase + s * A_STAGE + 0 * A_ARR;
        const uint32_t vst = sbase + s * A_STAGE + 1 * A_ARR;

#pragma unroll
        for (int half = 0; half < 2; half++) {
            const uint32_t kh_b = kst + half * (64 * 144);
            const uint32_t vh_b = vst + half * (64 * 144);

            float sac[8][4];
#pragma unroll
            for (int nt = 0; nt < 8; nt++)
#pragma unroll
                for (int i = 0; i < 4; i++) sac[nt][i] = 0.f;

#pragma unroll
            for (int kf = 0; kf < 4; kf++) {
#pragma unroll
                for (int np = 0; np < 4; np++) {
                    uint32_t off = (np * 16 + lr8) * 144 + kf * 32 + lc16;
                    uint32_t bh[4];
                    ldsm4(bh, kh_b + off);
                    uint32_t bA[2] = { bh[0], bh[2] }, bB[2] = { bh[1], bh[3] };
                    mma16816(sac[np * 2],     Qfh[kf], bA);
                    mma16816(sac[np * 2],     Qfl[kf], bA);
                    mma16816(sac[np * 2 + 1], Qfh[kf], bB);
                    mma16816(sac[np * 2 + 1], Qfl[kf], bB);
                }
            }

            float rs0 = 0.f, rs1 = 0.f;
#pragma unroll
            for (int nt = 0; nt < 8; nt++) {
                sac[nt][0] = ex2(sac[nt][0] - SM_OFF);
                sac[nt][1] = ex2(sac[nt][1] - SM_OFF);
                sac[nt][2] = ex2(sac[nt][2] - SM_OFF);
                sac[nt][3] = ex2(sac[nt][3] - SM_OFF);
                rs0 += sac[nt][0] + sac[nt][1];
                rs1 += sac[nt][2] + sac[nt][3];
            }
            l0 += rs0;
            l1 += rs1;

#pragma unroll
            for (int kf = 0; kf < 4; kf++) {
                uint32_t ph[4];
                ph[0] = cvt2h(sac[2 * kf][0],     sac[2 * kf][1]);
                ph[1] = cvt2h(sac[2 * kf][2],     sac[2 * kf][3]);
                ph[2] = cvt2h(sac[2 * kf + 1][0], sac[2 * kf + 1][1]);
                ph[3] = cvt2h(sac[2 * kf + 1][2], sac[2 * kf + 1][3]);
#pragma unroll
                for (int np = 0; np < 4; np++) {
                    uint32_t off = (kf * 16 + lr8) * 144 + np * 32 + lc16;
                    uint32_t vh[4];
                    ldsm4t(vh, vh_b + off);
                    uint32_t vA[2] = { vh[0], vh[1] }, vB[2] = { vh[2], vh[3] };
                    mma16816(oac[np * 2],     ph, vA);
                    mma16816(oac[np * 2 + 1], ph, vB);
                }
            }
        }
    }

#pragma unroll
    for (int off = 1; off <= 2; off <<= 1) {
        l0 += __shfl_xor_sync(0xffffffffu, l0, off);
        l1 += __shfl_xor_sync(0xffffffffu, l1, off);
    }
    float inv0 = 1.f / l0, inv1 = 1.f / l1;
    int row = q0 + wid * 16 + g;
    uint32_t* oh32 = (uint32_t*)(Ohi + base);
    uint32_t* ol32 = (uint32_t*)(Olo + base);
#pragma unroll
    for (int nt = 0; nt < 8; nt++) {
        int w = nt * 4 + j;
        uint32_t h, l;
        split2h(oac[nt][0] * inv0, oac[nt][1] * inv0, h, l);
        oh32[(size_t)row * (D_ / 2) + w] = h;
        ol32[(size_t)row * (D_ / 2) + w] = l;
        split2h(oac[nt][2] * inv1, oac[nt][3] * inv1, h, l);
        oh32[(size_t)(row + 8) * (D_ / 2) + w] = h;
        ol32[(size_t)(row + 8) * (D_ / 2) + w] = l;
    }
}

// ---------------------------------------------------------------------------
// Final-layer Wp on last tokens only.
// ---------------------------------------------------------------------------
__global__ void __launch_bounds__(256) hlast_kernel(
    const __half* __restrict__ Oh, const __half* __restrict__ Ol,
    const float* __restrict__ Wp3, float* __restrict__ hlast)
{
    __shared__ float os[D_];
    const int b = blockIdx.x;
    const size_t obase = ((size_t)b * T_ + (T_ - 1)) * D_;
    for (int d = threadIdx.x; d < D_; d += 256)
        os[d] = __half2float(Oh[obase + d]) + __half2float(Ol[obase + d]);
    __syncthreads();

    const float sD = 0.04419417382415922f;
    for (int od = threadIdx.x; od < D_; od += 256) {
        const float* w = Wp3 + (size_t)od * D_;
        float a0 = 0.f, a1 = 0.f, a2 = 0.f, a3 = 0.f;
        for (int k = 0; k < D_; k += 4) {
            float4 wv = *(const float4*)(w + k);
            a0 += wv.x * os[k];
            a1 += wv.y * os[k + 1];
            a2 += wv.z * os[k + 2];
            a3 += wv.w * os[k + 3];
        }
        hlast[b * D_ + od] = (a0 + a1 + a2 + a3) * sD;
    }
}

// ---------------------------------------------------------------------------
__global__ void __launch_bounds__(256) readout_kernel(
    const float* __restrict__ hlast, const float* __restrict__ R,
    float* __restrict__ out)
{
    __shared__ float hs[B_][D_];
    for (int i = threadIdx.x; i < B_ * D_; i += 256) {
        int b = i >> 9, d = i & 511;
        hs[b][d] = hlast[b * D_ + d];
    }
    __syncthreads();

    int v = blockIdx.x * 256 + threadIdx.x;
    float a0 = 0.f, a1 = 0.f, a2 = 0.f, a3 = 0.f;
    const float* r = R + (size_t)v * D_;
    for (int d = 0; d < D_; d += 4) {
        float4 rv = *(const float4*)(r + d);
        a0 += rv.x * hs[0][d] + rv.y * hs[0][d + 1] + rv.z * hs[0][d + 2] + rv.w * hs[0][d + 3];
        a1 += rv.x * hs[1][d] + rv.y * hs[1][d + 1] + rv.z * hs[1][d + 2] + rv.w * hs[1][d + 3];
        a2 += rv.x * hs[2][d] + rv.y * hs[2][d + 1] + rv.z * hs[2][d + 2] + rv.w * hs[2][d + 3];
        a3 += rv.x * hs[3][d] + rv.y * hs[3][d + 1] + rv.z * hs[3][d + 2] + rv.w * hs[3][d + 3];
    }
    const float sc = 0.04419417382415922f;
    out[0 * V_ + v] = a0 * sc;
    out[1 * V_ + v] = a1 * sc;
    out[2 * V_ + v] = a2 * sc;
    out[3 * V_ + v] = a3 * sc;
}

// ---------------------------------------------------------------------------
extern "C" void kernel_launch(void* const* d_in, const int* in_sizes, int n_in,
                              void* d_out, int out_size)
{
    const float* x  = (const float*)d_in[0];
    const float* te = (const float*)d_in[1];
    const float* pe = (const float*)d_in[2];
    const float* Wk = (const float*)d_in[3];
    const float* Wq = (const float*)d_in[4];
    const float* Wv = (const float*)d_in[5];
    const float* Wp = (const float*)d_in[6];
    const float* ro = (const float*)d_in[7];
    float* out = (float*)d_out;

    __half *hh, *hl, *qh, *ql, *k1, *v1, *oh, *ol;
    __half *te1, *wq1, *wk1, *wv1, *wpT, *uq, *uk, *uv;
    float* hlast;
    cudaGetSymbolAddress((void**)&hh,  g_hh);  cudaGetSymbolAddress((void**)&hl, g_hl);
    cudaGetSymbolAddress((void**)&qh,  g_qh);  cudaGetSymbolAddress((void**)&ql, g_ql);
    cudaGetSymbolAddress((void**)&k1,  g_k1);
    cudaGetSymbolAddress((void**)&v1,  g_v1);
    cudaGetSymbolAddress((void**)&oh,  g_oh);  cudaGetSymbolAddress((void**)&ol, g_ol);
    cudaGetSymbolAddress((void**)&te1, g_te1);
    cudaGetSymbolAddress((void**)&wq1, g_wq1);
    cudaGetSymbolAddress((void**)&wk1, g_wk1);
    cudaGetSymbolAddress((void**)&wv1, g_wv1);
    cudaGetSymbolAddress((void**)&wpT, g_wpT);
    cudaGetSymbolAddress((void**)&uq,  g_uq);
    cudaGetSymbolAddress((void**)&uk,  g_uk);
    cudaGetSymbolAddress((void**)&uv,  g_uv);
    cudaGetSymbolAddress((void**)&hlast, g_hlast);

    // attn_f16 uses 73.7KB dynamic smem
    cudaFuncSetAttribute(attn_f16, cudaFuncAttributeMaxDynamicSharedMemorySize, A_SMEM);

    const float sV = 0.022097086912079608f;  // 1/sqrt(2048)
    const float sD = 0.04419417382415922f;   // 1/sqrt(512)

    {
        int n4 = (D_ * V_) / 4;
        tohalf_kernel<<<(n4 + 255) / 256, 256>>>((const float4*)te, (uint2*)te1, n4);
        n4 = DD_ / 4;
        tohalf_kernel<<<(n4 + 255) / 256, 256>>>((const float4*)Wq, (uint2*)wq1, n4);
        tohalf_kernel<<<(n4 + 255) / 256, 256>>>((const float4*)Wk, (uint2*)wk1, n4);
        tohalf_kernel<<<(n4 + 255) / 256, 256>>>((const float4*)Wv, (uint2*)wv1, n4);
        transpose_kernel<<<dim3(16, 16, 3), 256>>>(Wp, wpT);
        gemm_combine<<<dim3(4, 4, 9), 256>>>(Wq, Wk, Wv, wpT, uq, uk, uv);
    }

    dim3 qkvgrid(D_ / 128, (B_ * T_) / 128, 3);

    // embed: h = x @ TE^T / sqrt(V) + pos
    gemm_nt_f32a<<<dim3(D_ / 128, (B_ * T_) / 128), 256>>>(
        x, te1, hh, hl, pe, B_ * T_, D_, V_, sV);

    for (int l = 0; l < L_; l++) {
        if (l == 0) {
            gemm_qkv<<<qkvgrid, 256>>>(hh, hl, wq1, wk1, wv1,
                                       qh, ql, k1, v1, sD);
        } else {
            size_t uo = (size_t)(l - 1) * DD_;
            gemm_qkv<<<qkvgrid, 256>>>(oh, ol, uq + uo, uk + uo, uv + uo,
                                       qh, ql, k1, v1, sD * sD);
        }

        attn_f16<<<dim3(T_ / 128, H_, B_), 256, A_SMEM>>>(qh, ql, k1, v1, oh, ol);
    }

    hlast_kernel<<<B_, 256>>>(oh, ol, Wp + (size_t)3 * DD_, hlast);
    readout_kernel<<<V_ / 256, 256>>>(hlast, ro, out);
}